// round 2
// baseline (speedup 1.0000x reference)
#include <cuda_runtime.h>

#define FOUT 64
#define KTOT 256
#define NMAX 100000
#define EMAX 3200000
#define TROWS 128
#define KC 32

// ---------------- scratch (device globals) ----------------
__device__ __align__(256) float g_h[NMAX * FOUT];   // 25.6 MB: h = xW
__device__ __align__(256) int   g_src[EMAX];        // 12.8 MB: src ids sorted by dst
__device__ int   g_cnt[NMAX];                       // histogram, then scatter cursor
__device__ int   g_off[NMAX + 1];                   // CSR offsets
__device__ float g_asrc[NMAX];
__device__ float g_adst[NMAX];

// ---------------- kernel 1: zero counters ----------------
__global__ void zero_cnt(int n) {
    int i = blockIdx.x * blockDim.x + threadIdx.x;
    if (i < n) g_cnt[i] = 0;
}

// ---------------- kernel 2: histogram of dst ----------------
__global__ void hist_kernel(const int* __restrict__ ei, int e) {
    int g = blockIdx.x * blockDim.x + threadIdx.x;
    if (g < e) atomicAdd(&g_cnt[ei[e + g]], 1);
}

// ---------------- kernel 3: single-block exclusive scan (n=100k) ----------------
__global__ __launch_bounds__(1024) void scan_kernel(int n) {
    __shared__ int warp_sums[32];
    int tid = threadIdx.x;
    int per = (n + 1023) / 1024;
    int start = tid * per;
    int end = min(start + per, n);
    if (end < start) end = start;

    int s = 0;
    for (int i = start; i < end; i++) s += g_cnt[i];

    // warp-level inclusive scan of s
    int lane = tid & 31, wid = tid >> 5;
    int v = s;
#pragma unroll
    for (int o = 1; o < 32; o <<= 1) {
        int t = __shfl_up_sync(0xffffffffu, v, o);
        if (lane >= o) v += t;
    }
    if (lane == 31) warp_sums[wid] = v;
    __syncthreads();
    if (wid == 0) {
        int w = (lane < 32) ? warp_sums[lane] : 0;
#pragma unroll
        for (int o = 1; o < 32; o <<= 1) {
            int t = __shfl_up_sync(0xffffffffu, w, o);
            if (lane >= o) w += t;
        }
        warp_sums[lane] = w;
    }
    __syncthreads();
    int base = v - s + (wid > 0 ? warp_sums[wid - 1] : 0);  // exclusive prefix for this thread

    int off = base;
    for (int i = start; i < end; i++) {
        int c = g_cnt[i];
        g_off[i] = off;
        g_cnt[i] = off;   // cursor for scatter
        off += c;
    }
    if (tid == 1023) g_off[n] = base + s;  // grand total = e
}

// ---------------- kernel 4: scatter src ids into CSR order ----------------
__global__ void scatter_kernel(const int* __restrict__ ei, int e) {
    int g = blockIdx.x * blockDim.x + threadIdx.x;
    if (g >= e) return;
    int src = ei[g];
    int dst = ei[e + g];
    int pos = atomicAdd(&g_cnt[dst], 1);
    g_src[pos] = src;
}

// ---------------- kernel 5: GEMM h = x@W + attention halves ----------------
__global__ __launch_bounds__(256) void gemm_kernel(
    const float* __restrict__ x, const float* __restrict__ W,
    const float* __restrict__ att_src, const float* __restrict__ att_dst, int n)
{
    __shared__ float xs[TROWS][KC + 1];
    __shared__ float ws[KC][FOUT];

    int tid = threadIdx.x;
    int tx = tid & 7;
    int ty = tid >> 3;
    int row0 = blockIdx.x * TROWS;

    float acc[4][8];
#pragma unroll
    for (int r = 0; r < 4; r++)
#pragma unroll
        for (int c = 0; c < 8; c++) acc[r][c] = 0.f;

    for (int k0 = 0; k0 < KTOT; k0 += KC) {
#pragma unroll
        for (int i = 0; i < 2; i++) {
            int kk = (tid >> 4) + i * 16;
            int cc = (tid & 15) * 4;
            *reinterpret_cast<float4*>(&ws[kk][cc]) =
                *reinterpret_cast<const float4*>(&W[(k0 + kk) * FOUT + cc]);
        }
        {
            int lr = tid >> 3;
            int kq = (tid & 7) * 4;
#pragma unroll
            for (int i = 0; i < 4; i++) {
                int row = row0 + lr + i * 32;
                float4 v = make_float4(0.f, 0.f, 0.f, 0.f);
                if (row < n)
                    v = *reinterpret_cast<const float4*>(&x[row * KTOT + k0 + kq]);
                xs[lr + i * 32][kq + 0] = v.x;
                xs[lr + i * 32][kq + 1] = v.y;
                xs[lr + i * 32][kq + 2] = v.z;
                xs[lr + i * 32][kq + 3] = v.w;
            }
        }
        __syncthreads();
#pragma unroll
        for (int k = 0; k < KC; k++) {
            float4 w0 = *reinterpret_cast<const float4*>(&ws[k][tx * 8]);
            float4 w1 = *reinterpret_cast<const float4*>(&ws[k][tx * 8 + 4]);
#pragma unroll
            for (int r = 0; r < 4; r++) {
                float xv = xs[ty * 4 + r][k];
                acc[r][0] += xv * w0.x; acc[r][1] += xv * w0.y;
                acc[r][2] += xv * w0.z; acc[r][3] += xv * w0.w;
                acc[r][4] += xv * w1.x; acc[r][5] += xv * w1.y;
                acc[r][6] += xv * w1.z; acc[r][7] += xv * w1.w;
            }
        }
        __syncthreads();
    }

    float4 as0 = *reinterpret_cast<const float4*>(&att_src[tx * 8]);
    float4 as1 = *reinterpret_cast<const float4*>(&att_src[tx * 8 + 4]);
    float4 ad0 = *reinterpret_cast<const float4*>(&att_dst[tx * 8]);
    float4 ad1 = *reinterpret_cast<const float4*>(&att_dst[tx * 8 + 4]);

#pragma unroll
    for (int r = 0; r < 4; r++) {
        int row = row0 + ty * 4 + r;
        float ps = acc[r][0] * as0.x + acc[r][1] * as0.y + acc[r][2] * as0.z + acc[r][3] * as0.w
                 + acc[r][4] * as1.x + acc[r][5] * as1.y + acc[r][6] * as1.z + acc[r][7] * as1.w;
        float pd = acc[r][0] * ad0.x + acc[r][1] * ad0.y + acc[r][2] * ad0.z + acc[r][3] * ad0.w
                 + acc[r][4] * ad1.x + acc[r][5] * ad1.y + acc[r][6] * ad1.z + acc[r][7] * ad1.w;
#pragma unroll
        for (int o = 1; o < 8; o <<= 1) {
            ps += __shfl_xor_sync(0xffffffffu, ps, o);
            pd += __shfl_xor_sync(0xffffffffu, pd, o);
        }
        if (row < n) {
            *reinterpret_cast<float4*>(&g_h[row * FOUT + tx * 8]) =
                make_float4(acc[r][0], acc[r][1], acc[r][2], acc[r][3]);
            *reinterpret_cast<float4*>(&g_h[row * FOUT + tx * 8 + 4]) =
                make_float4(acc[r][4], acc[r][5], acc[r][6], acc[r][7]);
            if (tx == 0) { g_asrc[row] = ps; g_adst[row] = pd; }
        }
    }
}

// ---------------- kernel 6: per-node gather aggregation (1 warp/node) ----------------
__global__ __launch_bounds__(256) void aggregate_kernel(
    float* __restrict__ out, const float* __restrict__ bias, int n)
{
    int warp = (blockIdx.x * blockDim.x + threadIdx.x) >> 5;
    if (warp >= n) return;
    int lane = threadIdx.x & 31;
    int half = lane >> 4;
    int l = lane & 15;
    int i = warp;

    int rs = g_off[i];
    int re = g_off[i + 1];
    float adst = g_adst[i];

    float e_self = g_asrc[i] + adst;
    e_self = e_self > 0.f ? e_self : 0.2f * e_self;

    // pass 1: segment max (self-loop included via init)
    float m = e_self;
    for (int j = rs + lane; j < re; j += 32) {
        int s = g_src[j];
        float v = g_asrc[s] + adst;
        v = v > 0.f ? v : 0.2f * v;
        m = fmaxf(m, v);
    }
#pragma unroll
    for (int o = 16; o > 0; o >>= 1)
        m = fmaxf(m, __shfl_xor_sync(0xffffffffu, m, o));

    // pass 2: exp + weighted accumulate. Two edges in flight (one per half-warp).
    float4 acc = make_float4(0.f, 0.f, 0.f, 0.f);
    float dsum = 0.f;
    int deg = re - rs;
    const float4* h4 = reinterpret_cast<const float4*>(g_h);

    for (int t = half; t < deg; t += 2) {
        int s = g_src[rs + t];
        float v = g_asrc[s] + adst;
        v = v > 0.f ? v : 0.2f * v;
        float p = __expf(v - m);
        if (l == 0) dsum += p;
        float4 hv = h4[(size_t)s * 16 + l];
        acc.x += p * hv.x; acc.y += p * hv.y;
        acc.z += p * hv.z; acc.w += p * hv.w;
    }
    // self-loop on half 0
    if (half == 0) {
        float p = __expf(e_self - m);
        if (l == 0) dsum += p;
        float4 hv = h4[(size_t)i * 16 + l];
        acc.x += p * hv.x; acc.y += p * hv.y;
        acc.z += p * hv.z; acc.w += p * hv.w;
    }

    // combine halves
    dsum += __shfl_xor_sync(0xffffffffu, dsum, 16);
    dsum = __shfl_sync(0xffffffffu, dsum, 0);
    acc.x += __shfl_down_sync(0xffffffffu, acc.x, 16);
    acc.y += __shfl_down_sync(0xffffffffu, acc.y, 16);
    acc.z += __shfl_down_sync(0xffffffffu, acc.z, 16);
    acc.w += __shfl_down_sync(0xffffffffu, acc.w, 16);

    if (half == 0) {
        float inv = 1.0f / (dsum + 1e-16f);
        float4 b = reinterpret_cast<const float4*>(bias)[l];
        reinterpret_cast<float4*>(out)[(size_t)i * 16 + l] =
            make_float4(acc.x * inv + b.x, acc.y * inv + b.y,
                        acc.z * inv + b.z, acc.w * inv + b.w);
    }
}

// ---------------- launch ----------------
extern "C" void kernel_launch(void* const* d_in, const int* in_sizes, int n_in,
                              void* d_out, int out_size) {
    const float* x       = (const float*)d_in[0];
    const int*   ei      = (const int*)d_in[1];
    const float* W       = (const float*)d_in[2];
    const float* att_src = (const float*)d_in[3];
    const float* att_dst = (const float*)d_in[4];
    const float* bias    = (const float*)d_in[5];
    float* out = (float*)d_out;

    int n = in_sizes[0] / KTOT;   // 100000
    int e = in_sizes[1] / 2;      // 3200000

    zero_cnt<<<(n + 255) / 256, 256>>>(n);
    hist_kernel<<<(e + 255) / 256, 256>>>(ei, e);
    scan_kernel<<<1, 1024>>>(n);
    scatter_kernel<<<(e + 255) / 256, 256>>>(ei, e);

    gemm_kernel<<<(n + TROWS - 1) / TROWS, 256>>>(x, W, att_src, att_dst, n);

    long long tagg = (long long)n * 32;
    aggregate_kernel<<<(int)((tagg + 255) / 256), 256>>>(out, bias, n);
}

// round 3
// speedup vs baseline: 1.0233x; 1.0233x over previous
#include <cuda_runtime.h>

#define FOUT 64
#define KTOT 256
#define NMAX 100000
#define EMAX 3200000
#define TROWS 128
#define KC 32

// ---------------- scratch (device globals) ----------------
__device__ __align__(256) float g_h[NMAX * FOUT];   // 25.6 MB: h = xW
__device__ __align__(256) int   g_src[EMAX];        // 12.8 MB: src ids sorted by dst
__device__ int   g_cnt[NMAX];                       // histogram, then scatter cursor
__device__ int   g_off[NMAX + 1];                   // CSR offsets
__device__ float g_asrc[NMAX];
__device__ float g_adst[NMAX];

// ---------------- kernel 1: zero counters ----------------
__global__ void zero_cnt(int n) {
    int i = blockIdx.x * blockDim.x + threadIdx.x;
    if (i < n) g_cnt[i] = 0;
}

// ---------------- kernel 2: histogram of dst ----------------
__global__ void hist_kernel(const int* __restrict__ ei, int e) {
    int g = blockIdx.x * blockDim.x + threadIdx.x;
    if (g < e) atomicAdd(&g_cnt[ei[e + g]], 1);
}

// ---------------- kernel 3: single-block exclusive scan (n=100k) ----------------
__global__ __launch_bounds__(1024) void scan_kernel(int n) {
    __shared__ int warp_sums[32];
    int tid = threadIdx.x;
    int per = (n + 1023) / 1024;
    int start = tid * per;
    int end = min(start + per, n);
    if (end < start) end = start;

    int s = 0;
    for (int i = start; i < end; i++) s += g_cnt[i];

    int lane = tid & 31, wid = tid >> 5;
    int v = s;
#pragma unroll
    for (int o = 1; o < 32; o <<= 1) {
        int t = __shfl_up_sync(0xffffffffu, v, o);
        if (lane >= o) v += t;
    }
    if (lane == 31) warp_sums[wid] = v;
    __syncthreads();
    if (wid == 0) {
        int w = warp_sums[lane];
#pragma unroll
        for (int o = 1; o < 32; o <<= 1) {
            int t = __shfl_up_sync(0xffffffffu, w, o);
            if (lane >= o) w += t;
        }
        warp_sums[lane] = w;
    }
    __syncthreads();
    int base = v - s + (wid > 0 ? warp_sums[wid - 1] : 0);

    int off = base;
    for (int i = start; i < end; i++) {
        int c = g_cnt[i];
        g_off[i] = off;
        g_cnt[i] = off;   // cursor for scatter
        off += c;
    }
    if (tid == 1023) g_off[n] = base + s;
}

// ---------------- kernel 4: scatter src ids into CSR order ----------------
__global__ void scatter_kernel(const int* __restrict__ ei, int e) {
    int g = blockIdx.x * blockDim.x + threadIdx.x;
    if (g >= e) return;
    int src = ei[g];
    int dst = ei[e + g];
    int pos = atomicAdd(&g_cnt[dst], 1);
    g_src[pos] = src;
}

// ---------------- kernel 5: GEMM h = x@W + attention halves ----------------
__global__ __launch_bounds__(256) void gemm_kernel(
    const float* __restrict__ x, const float* __restrict__ W,
    const float* __restrict__ att_src, const float* __restrict__ att_dst, int n)
{
    __shared__ float xs[TROWS][KC + 1];
    __shared__ float ws[KC][FOUT];

    int tid = threadIdx.x;
    int tx = tid & 7;
    int ty = tid >> 3;
    int row0 = blockIdx.x * TROWS;

    float acc[4][8];
#pragma unroll
    for (int r = 0; r < 4; r++)
#pragma unroll
        for (int c = 0; c < 8; c++) acc[r][c] = 0.f;

    for (int k0 = 0; k0 < KTOT; k0 += KC) {
#pragma unroll
        for (int i = 0; i < 2; i++) {
            int kk = (tid >> 4) + i * 16;
            int cc = (tid & 15) * 4;
            *reinterpret_cast<float4*>(&ws[kk][cc]) =
                *reinterpret_cast<const float4*>(&W[(k0 + kk) * FOUT + cc]);
        }
        {
            int lr = tid >> 3;
            int kq = (tid & 7) * 4;
#pragma unroll
            for (int i = 0; i < 4; i++) {
                int row = row0 + lr + i * 32;
                float4 v = make_float4(0.f, 0.f, 0.f, 0.f);
                if (row < n)
                    v = *reinterpret_cast<const float4*>(&x[row * KTOT + k0 + kq]);
                xs[lr + i * 32][kq + 0] = v.x;
                xs[lr + i * 32][kq + 1] = v.y;
                xs[lr + i * 32][kq + 2] = v.z;
                xs[lr + i * 32][kq + 3] = v.w;
            }
        }
        __syncthreads();
#pragma unroll
        for (int k = 0; k < KC; k++) {
            float4 w0 = *reinterpret_cast<const float4*>(&ws[k][tx * 8]);
            float4 w1 = *reinterpret_cast<const float4*>(&ws[k][tx * 8 + 4]);
#pragma unroll
            for (int r = 0; r < 4; r++) {
                float xv = xs[ty * 4 + r][k];
                acc[r][0] += xv * w0.x; acc[r][1] += xv * w0.y;
                acc[r][2] += xv * w0.z; acc[r][3] += xv * w0.w;
                acc[r][4] += xv * w1.x; acc[r][5] += xv * w1.y;
                acc[r][6] += xv * w1.z; acc[r][7] += xv * w1.w;
            }
        }
        __syncthreads();
    }

    float4 as0 = *reinterpret_cast<const float4*>(&att_src[tx * 8]);
    float4 as1 = *reinterpret_cast<const float4*>(&att_src[tx * 8 + 4]);
    float4 ad0 = *reinterpret_cast<const float4*>(&att_dst[tx * 8]);
    float4 ad1 = *reinterpret_cast<const float4*>(&att_dst[tx * 8 + 4]);

#pragma unroll
    for (int r = 0; r < 4; r++) {
        int row = row0 + ty * 4 + r;
        float ps = acc[r][0] * as0.x + acc[r][1] * as0.y + acc[r][2] * as0.z + acc[r][3] * as0.w
                 + acc[r][4] * as1.x + acc[r][5] * as1.y + acc[r][6] * as1.z + acc[r][7] * as1.w;
        float pd = acc[r][0] * ad0.x + acc[r][1] * ad0.y + acc[r][2] * ad0.z + acc[r][3] * ad0.w
                 + acc[r][4] * ad1.x + acc[r][5] * ad1.y + acc[r][6] * ad1.z + acc[r][7] * ad1.w;
#pragma unroll
        for (int o = 1; o < 8; o <<= 1) {
            ps += __shfl_xor_sync(0xffffffffu, ps, o);
            pd += __shfl_xor_sync(0xffffffffu, pd, o);
        }
        if (row < n) {
            *reinterpret_cast<float4*>(&g_h[row * FOUT + tx * 8]) =
                make_float4(acc[r][0], acc[r][1], acc[r][2], acc[r][3]);
            *reinterpret_cast<float4*>(&g_h[row * FOUT + tx * 8 + 4]) =
                make_float4(acc[r][4], acc[r][5], acc[r][6], acc[r][7]);
            if (tx == 0) { g_asrc[row] = ps; g_adst[row] = pd; }
        }
    }
}

// ---------------- kernel 6: gather aggregation, 1 warp/node, smem-staged edges ----------------
// No max-subtraction: softmax ratio exp(e)/sum(exp(e)) is identical and |e| <= ~10.
__global__ __launch_bounds__(256) void aggregate_kernel(
    float* __restrict__ out, const float* __restrict__ bias, int n)
{
    __shared__ int   s_s[8][32];
    __shared__ float p_s[8][32];

    int w = threadIdx.x >> 5;
    int lane = threadIdx.x & 31;
    int node = blockIdx.x * 8 + w;
    if (node >= n) return;

    int rs = g_off[node];
    int re = g_off[node + 1];
    float adst = g_adst[node];

    const float2* __restrict__ h2 = reinterpret_cast<const float2*>(g_h);
    float2 acc = make_float2(0.f, 0.f);
    float dsum = 0.f;

    for (int base = rs; base < re; base += 32) {
        int cnt = min(32, re - base);
        int s = 0;
        float p = 0.f;
        if (lane < cnt) {
            s = g_src[base + lane];
            float v = g_asrc[s] + adst;
            v = v > 0.f ? v : 0.2f * v;
            p = __expf(v);
        }
        dsum += p;
        s_s[w][lane] = s;
        p_s[w][lane] = p;
        __syncwarp();
#pragma unroll 4
        for (int t = 0; t < cnt; t++) {
            int st = s_s[w][t];
            float pt = p_s[w][t];
            float2 hv = h2[(size_t)st * 32 + lane];
            acc.x += pt * hv.x;
            acc.y += pt * hv.y;
        }
        __syncwarp();
    }

    // self-loop
    {
        float v = g_asrc[node] + adst;
        v = v > 0.f ? v : 0.2f * v;
        float p = __expf(v);
        if (lane == 0) dsum += p;
        float2 hv = h2[(size_t)node * 32 + lane];
        acc.x += p * hv.x;
        acc.y += p * hv.y;
    }

#pragma unroll
    for (int o = 16; o > 0; o >>= 1)
        dsum += __shfl_xor_sync(0xffffffffu, dsum, o);

    float inv = 1.0f / (dsum + 1e-16f);
    float2 b = reinterpret_cast<const float2*>(bias)[lane];
    reinterpret_cast<float2*>(out)[(size_t)node * 32 + lane] =
        make_float2(acc.x * inv + b.x, acc.y * inv + b.y);
}

// ---------------- launch: fork CSR build ∥ GEMM, join before aggregate ----------------
extern "C" void kernel_launch(void* const* d_in, const int* in_sizes, int n_in,
                              void* d_out, int out_size) {
    const float* x       = (const float*)d_in[0];
    const int*   ei      = (const int*)d_in[1];
    const float* W       = (const float*)d_in[2];
    const float* att_src = (const float*)d_in[3];
    const float* att_dst = (const float*)d_in[4];
    const float* bias    = (const float*)d_in[5];
    float* out = (float*)d_out;

    int n = in_sizes[0] / KTOT;   // 100000
    int e = in_sizes[1] / 2;      // 3200000

    // one-time side stream + fork/join events (created before any capture;
    // every call performs the identical launch sequence)
    static cudaStream_t s2 = nullptr;
    static cudaEvent_t evFork = nullptr, evJoin = nullptr;
    if (s2 == nullptr) {
        cudaStreamCreateWithFlags(&s2, cudaStreamNonBlocking);
        cudaEventCreateWithFlags(&evFork, cudaEventDisableTiming);
        cudaEventCreateWithFlags(&evJoin, cudaEventDisableTiming);
    }

    bool forked = (s2 != nullptr && evFork != nullptr && evJoin != nullptr);

    if (forked) {
        // fork: GEMM runs on s2 concurrently with CSR build on the origin stream
        cudaEventRecord(evFork, 0);
        cudaStreamWaitEvent(s2, evFork, 0);
        gemm_kernel<<<(n + TROWS - 1) / TROWS, 256, 0, s2>>>(x, W, att_src, att_dst, n);
        cudaEventRecord(evJoin, s2);
    }

    // CSR build on origin stream
    zero_cnt<<<(n + 255) / 256, 256>>>(n);
    hist_kernel<<<(e + 255) / 256, 256>>>(ei, e);
    scan_kernel<<<1, 1024>>>(n);
    scatter_kernel<<<(e + 255) / 256, 256>>>(ei, e);

    if (forked) {
        cudaStreamWaitEvent(0, evJoin, 0);
    } else {
        gemm_kernel<<<(n + TROWS - 1) / TROWS, 256>>>(x, W, att_src, att_dst, n);
    }

    aggregate_kernel<<<(n + 7) / 8, 256>>>(out, bias, n);
}

// round 5
// speedup vs baseline: 1.6997x; 1.6609x over previous
#include <cuda_runtime.h>

#define FOUT 64
#define KTOT 256
#define NMAX 100000
#define EMAX 3200000
#define TROWS 128
#define KC 32
#define SCAN_B 1024
#define NB ((NMAX + SCAN_B - 1) / SCAN_B)   // 98 blocks

// ---------------- scratch (device globals) ----------------
__device__ __align__(256) float g_h[NMAX * FOUT];   // 25.6 MB: h = xW
__device__ __align__(256) int   g_src[EMAX];        // 12.8 MB: src ids sorted by dst
__device__ int   g_cnt[NMAX];                       // histogram, then scatter cursor
__device__ int   g_off[NMAX + 1];                   // CSR offsets
__device__ int   g_bsum[NB];
__device__ int   g_bbase[NB];
__device__ float g_asrc[NMAX];
__device__ float g_adst[NMAX];

// ---------------- kernel 1: zero counters ----------------
__global__ void zero_cnt(int n) {
    int i = blockIdx.x * blockDim.x + threadIdx.x;
    if (i < n) g_cnt[i] = 0;
}

// ---------------- kernel 2: histogram of dst ----------------
__global__ void hist_kernel(const int* __restrict__ ei, int e) {
    int g = blockIdx.x * blockDim.x + threadIdx.x;
    if (g < e) atomicAdd(&g_cnt[ei[e + g]], 1);
}

// ---------------- scan phase 1: per-block sums ----------------
__global__ __launch_bounds__(SCAN_B) void scan_p1(int n) {
    __shared__ int wsum[32];
    int i = blockIdx.x * SCAN_B + threadIdx.x;
    int c = (i < n) ? g_cnt[i] : 0;
    int lane = threadIdx.x & 31, wid = threadIdx.x >> 5;
    int v = c;
#pragma unroll
    for (int o = 16; o > 0; o >>= 1) v += __shfl_xor_sync(0xffffffffu, v, o);
    if (lane == 0) wsum[wid] = v;
    __syncthreads();
    if (wid == 0) {
        int w = wsum[lane];
#pragma unroll
        for (int o = 16; o > 0; o >>= 1) w += __shfl_xor_sync(0xffffffffu, w, o);
        if (lane == 0) g_bsum[blockIdx.x] = w;
    }
}

// ---------------- scan phase 2: scan the NB block sums (1 block) ----------------
__global__ __launch_bounds__(128) void scan_p2(int n, int e) {
    __shared__ int wpre[4];
    int tid = threadIdx.x;
    int lane = tid & 31, wid = tid >> 5;
    int s = (tid < NB) ? g_bsum[tid] : 0;
    int v = s;
#pragma unroll
    for (int o = 1; o < 32; o <<= 1) {
        int t = __shfl_up_sync(0xffffffffu, v, o);
        if (lane >= o) v += t;
    }
    if (lane == 31) wpre[wid] = v;
    __syncthreads();
    if (tid == 0) {
        int a = 0;
#pragma unroll
        for (int k = 0; k < 4; k++) { int t = wpre[k]; wpre[k] = a; a += t; }
    }
    __syncthreads();
    if (tid < NB) g_bbase[tid] = v - s + wpre[wid];
    if (tid == 0) g_off[n] = e;
}

// ---------------- scan phase 3: local exclusive scan + base, write offsets/cursors ----------------
__global__ __launch_bounds__(SCAN_B) void scan_p3(int n) {
    __shared__ int wsum[32];
    int i = blockIdx.x * SCAN_B + threadIdx.x;
    int c = (i < n) ? g_cnt[i] : 0;
    int lane = threadIdx.x & 31, wid = threadIdx.x >> 5;
    int v = c;
#pragma unroll
    for (int o = 1; o < 32; o <<= 1) {
        int t = __shfl_up_sync(0xffffffffu, v, o);
        if (lane >= o) v += t;
    }
    if (lane == 31) wsum[wid] = v;
    __syncthreads();
    if (wid == 0) {
        int w = wsum[lane];
#pragma unroll
        for (int o = 1; o < 32; o <<= 1) {
            int t = __shfl_up_sync(0xffffffffu, w, o);
            if (lane >= o) w += t;
        }
        wsum[lane] = w;
    }
    __syncthreads();
    int excl = v - c + (wid > 0 ? wsum[wid - 1] : 0);
    int off = g_bbase[blockIdx.x] + excl;
    if (i < n) { g_off[i] = off; g_cnt[i] = off; }
}

// ---------------- kernel 4: scatter src ids into CSR order ----------------
__global__ void scatter_kernel(const int* __restrict__ ei, int e) {
    int g = blockIdx.x * blockDim.x + threadIdx.x;
    if (g >= e) return;
    int src = ei[g];
    int dst = ei[e + g];
    int pos = atomicAdd(&g_cnt[dst], 1);
    g_src[pos] = src;
}

// ---------------- kernel 5: GEMM h = x@W + attention halves ----------------
__global__ __launch_bounds__(256) void gemm_kernel(
    const float* __restrict__ x, const float* __restrict__ W,
    const float* __restrict__ att_src, const float* __restrict__ att_dst, int n)
{
    __shared__ float xs[TROWS][KC + 1];
    __shared__ float ws[KC][FOUT];

    int tid = threadIdx.x;
    int tx = tid & 7;
    int ty = tid >> 3;
    int row0 = blockIdx.x * TROWS;

    float acc[4][8];
#pragma unroll
    for (int r = 0; r < 4; r++)
#pragma unroll
        for (int c = 0; c < 8; c++) acc[r][c] = 0.f;

    for (int k0 = 0; k0 < KTOT; k0 += KC) {
#pragma unroll
        for (int i = 0; i < 2; i++) {
            int kk = (tid >> 4) + i * 16;
            int cc = (tid & 15) * 4;
            *reinterpret_cast<float4*>(&ws[kk][cc]) =
                *reinterpret_cast<const float4*>(&W[(k0 + kk) * FOUT + cc]);
        }
        {
            int lr = tid >> 3;
            int kq = (tid & 7) * 4;
#pragma unroll
            for (int i = 0; i < 4; i++) {
                int row = row0 + lr + i * 32;
                float4 v = make_float4(0.f, 0.f, 0.f, 0.f);
                if (row < n)
                    v = *reinterpret_cast<const float4*>(&x[row * KTOT + k0 + kq]);
                xs[lr + i * 32][kq + 0] = v.x;
                xs[lr + i * 32][kq + 1] = v.y;
                xs[lr + i * 32][kq + 2] = v.z;
                xs[lr + i * 32][kq + 3] = v.w;
            }
        }
        __syncthreads();
#pragma unroll
        for (int k = 0; k < KC; k++) {
            float4 w0 = *reinterpret_cast<const float4*>(&ws[k][tx * 8]);
            float4 w1 = *reinterpret_cast<const float4*>(&ws[k][tx * 8 + 4]);
#pragma unroll
            for (int r = 0; r < 4; r++) {
                float xv = xs[ty * 4 + r][k];
                acc[r][0] += xv * w0.x; acc[r][1] += xv * w0.y;
                acc[r][2] += xv * w0.z; acc[r][3] += xv * w0.w;
                acc[r][4] += xv * w1.x; acc[r][5] += xv * w1.y;
                acc[r][6] += xv * w1.z; acc[r][7] += xv * w1.w;
            }
        }
        __syncthreads();
    }

    float4 as0 = *reinterpret_cast<const float4*>(&att_src[tx * 8]);
    float4 as1 = *reinterpret_cast<const float4*>(&att_src[tx * 8 + 4]);
    float4 ad0 = *reinterpret_cast<const float4*>(&att_dst[tx * 8]);
    float4 ad1 = *reinterpret_cast<const float4*>(&att_dst[tx * 8 + 4]);

#pragma unroll
    for (int r = 0; r < 4; r++) {
        int row = row0 + ty * 4 + r;
        float ps = acc[r][0] * as0.x + acc[r][1] * as0.y + acc[r][2] * as0.z + acc[r][3] * as0.w
                 + acc[r][4] * as1.x + acc[r][5] * as1.y + acc[r][6] * as1.z + acc[r][7] * as1.w;
        float pd = acc[r][0] * ad0.x + acc[r][1] * ad0.y + acc[r][2] * ad0.z + acc[r][3] * ad0.w
                 + acc[r][4] * ad1.x + acc[r][5] * ad1.y + acc[r][6] * ad1.z + acc[r][7] * ad1.w;
#pragma unroll
        for (int o = 1; o < 8; o <<= 1) {
            ps += __shfl_xor_sync(0xffffffffu, ps, o);
            pd += __shfl_xor_sync(0xffffffffu, pd, o);
        }
        if (row < n) {
            *reinterpret_cast<float4*>(&g_h[row * FOUT + tx * 8]) =
                make_float4(acc[r][0], acc[r][1], acc[r][2], acc[r][3]);
            *reinterpret_cast<float4*>(&g_h[row * FOUT + tx * 8 + 4]) =
                make_float4(acc[r][4], acc[r][5], acc[r][6], acc[r][7]);
            if (tx == 0) { g_asrc[row] = ps; g_adst[row] = pd; }
        }
    }
}

// ---------------- kernel 6: gather aggregation, 1 warp/node, float4 lanes, 2 edges/iter ----------------
// No max-subtraction: softmax ratio exp(e)/sum(exp(e)) is identical; |logit| is small.
__global__ __launch_bounds__(256) void aggregate_kernel(
    float* __restrict__ out, const float* __restrict__ bias, int n)
{
    __shared__ int   s_s[8][32];
    __shared__ float p_s[8][32];

    int w = threadIdx.x >> 5;
    int lane = threadIdx.x & 31;
    int half = lane >> 4;
    int l = lane & 15;
    int node = blockIdx.x * 8 + w;
    if (node >= n) return;

    int rs = g_off[node];
    int re = g_off[node + 1];
    float adst = g_adst[node];

    const float4* __restrict__ h4 = reinterpret_cast<const float4*>(g_h);
    float4 acc = make_float4(0.f, 0.f, 0.f, 0.f);
    float dsum = 0.f;

    for (int base = rs; base < re; base += 32) {
        int cnt = min(32, re - base);
        int s = 0;
        float p = 0.f;
        if (lane < cnt) {
            s = g_src[base + lane];
            float v = g_asrc[s] + adst;
            v = v > 0.f ? v : 0.2f * v;
            p = __expf(v);
        }
        dsum += p;
        s_s[w][lane] = s;
        p_s[w][lane] = p;
        __syncwarp();
        // two edges in flight per iteration: half 0 takes even t, half 1 odd t
#pragma unroll 4
        for (int t = half; t < cnt; t += 2) {
            int st = s_s[w][t];
            float pt = p_s[w][t];
            float4 hv = h4[(size_t)st * 16 + l];
            acc.x += pt * hv.x; acc.y += pt * hv.y;
            acc.z += pt * hv.z; acc.w += pt * hv.w;
        }
        __syncwarp();
    }

    // self-loop (half 0 only)
    if (half == 0) {
        float v = g_asrc[node] + adst;
        v = v > 0.f ? v : 0.2f * v;
        float p = __expf(v);
        if (l == 0) dsum += p;
        float4 hv = h4[(size_t)node * 16 + l];
        acc.x += p * hv.x; acc.y += p * hv.y;
        acc.z += p * hv.z; acc.w += p * hv.w;
    }

    // full-warp denom reduction
#pragma unroll
    for (int o = 16; o > 0; o >>= 1)
        dsum += __shfl_xor_sync(0xffffffffu, dsum, o);

    // combine the two half-warps' partial rows
    acc.x += __shfl_down_sync(0xffffffffu, acc.x, 16);
    acc.y += __shfl_down_sync(0xffffffffu, acc.y, 16);
    acc.z += __shfl_down_sync(0xffffffffu, acc.z, 16);
    acc.w += __shfl_down_sync(0xffffffffu, acc.w, 16);

    if (half == 0) {
        float inv = 1.0f / (dsum + 1e-16f);
        float4 b = reinterpret_cast<const float4*>(bias)[l];
        reinterpret_cast<float4*>(out)[(size_t)node * 16 + l] =
            make_float4(acc.x * inv + b.x, acc.y * inv + b.y,
                        acc.z * inv + b.z, acc.w * inv + b.w);
    }
}

// ---------------- launch: fork CSR build ∥ GEMM, join before aggregate ----------------
extern "C" void kernel_launch(void* const* d_in, const int* in_sizes, int n_in,
                              void* d_out, int out_size) {
    const float* x       = (const float*)d_in[0];
    const int*   ei      = (const int*)d_in[1];
    const float* W       = (const float*)d_in[2];
    const float* att_src = (const float*)d_in[3];
    const float* att_dst = (const float*)d_in[4];
    const float* bias    = (const float*)d_in[5];
    float* out = (float*)d_out;

    int n = in_sizes[0] / KTOT;   // 100000
    int e = in_sizes[1] / 2;      // 3200000

    static cudaStream_t s2 = nullptr;
    static cudaEvent_t evFork = nullptr, evJoin = nullptr;
    if (s2 == nullptr) {
        cudaStreamCreateWithFlags(&s2, cudaStreamNonBlocking);
        cudaEventCreateWithFlags(&evFork, cudaEventDisableTiming);
        cudaEventCreateWithFlags(&evJoin, cudaEventDisableTiming);
    }

    // fork: GEMM on side stream, CSR build on origin stream
    cudaEventRecord(evFork, 0);
    cudaStreamWaitEvent(s2, evFork, 0);
    gemm_kernel<<<(n + TROWS - 1) / TROWS, 256, 0, s2>>>(x, W, att_src, att_dst, n);
    cudaEventRecord(evJoin, s2);

    zero_cnt<<<(n + 255) / 256, 256>>>(n);
    hist_kernel<<<(e + 255) / 256, 256>>>(ei, e);
    scan_p1<<<NB, SCAN_B>>>(n);
    scan_p2<<<1, 128>>>(n, e);
    scan_p3<<<NB, SCAN_B>>>(n);
    scatter_kernel<<<(e + 255) / 256, 256>>>(ei, e);

    cudaStreamWaitEvent(0, evJoin, 0);

    aggregate_kernel<<<(n + 7) / 8, 256>>>(out, bias, n);
}

// round 7
// speedup vs baseline: 1.7233x; 1.0139x over previous
#include <cuda_runtime.h>
#include <cuda_fp16.h>

#define FOUT 64
#define KTOT 256
#define NMAX 100000
#define EMAX 3200000
#define TROWS 128
#define KC 32
#define SCAN_B 1024
#define NB ((NMAX + SCAN_B - 1) / SCAN_B)   // 98 blocks

// ---------------- scratch (device globals) ----------------
__device__ __align__(256) __half g_hh[NMAX * FOUT]; // 12.8 MB: h = xW (fp16, gather copy)
__device__ __align__(256) int    g_src[EMAX];       // 12.8 MB: src ids sorted by dst
__device__ int   g_cnt[NMAX];
__device__ int   g_off[NMAX + 1];
__device__ int   g_bsum[NB];
__device__ int   g_bbase[NB];
__device__ float g_asrc[NMAX];
__device__ float g_adst[NMAX];

#define FMA2(acc, w, xv) \
    asm("fma.rn.f32x2 %0, %1, %2, %0;" : "+l"(acc) : "l"(w), "l"(xv))

// ---------------- kernel 1: zero counters ----------------
__global__ void zero_cnt(int n) {
    int i = blockIdx.x * blockDim.x + threadIdx.x;
    if (i < n) g_cnt[i] = 0;
}

// ---------------- kernel 2: histogram of dst ----------------
__global__ void hist_kernel(const int* __restrict__ ei, int e) {
    int g = blockIdx.x * blockDim.x + threadIdx.x;
    if (g < e) atomicAdd(&g_cnt[ei[e + g]], 1);
}

// ---------------- scan phase 1: per-block sums ----------------
__global__ __launch_bounds__(SCAN_B) void scan_p1(int n) {
    __shared__ int wsum[32];
    int i = blockIdx.x * SCAN_B + threadIdx.x;
    int c = (i < n) ? g_cnt[i] : 0;
    int lane = threadIdx.x & 31, wid = threadIdx.x >> 5;
    int v = c;
#pragma unroll
    for (int o = 16; o > 0; o >>= 1) v += __shfl_xor_sync(0xffffffffu, v, o);
    if (lane == 0) wsum[wid] = v;
    __syncthreads();
    if (wid == 0) {
        int w = wsum[lane];
#pragma unroll
        for (int o = 16; o > 0; o >>= 1) w += __shfl_xor_sync(0xffffffffu, w, o);
        if (lane == 0) g_bsum[blockIdx.x] = w;
    }
}

// ---------------- scan phase 2: scan the NB block sums (1 block) ----------------
__global__ __launch_bounds__(128) void scan_p2(int n, int e) {
    __shared__ int wpre[4];
    int tid = threadIdx.x;
    int lane = tid & 31, wid = tid >> 5;
    int s = (tid < NB) ? g_bsum[tid] : 0;
    int v = s;
#pragma unroll
    for (int o = 1; o < 32; o <<= 1) {
        int t = __shfl_up_sync(0xffffffffu, v, o);
        if (lane >= o) v += t;
    }
    if (lane == 31) wpre[wid] = v;
    __syncthreads();
    if (tid == 0) {
        int a = 0;
#pragma unroll
        for (int k = 0; k < 4; k++) { int t = wpre[k]; wpre[k] = a; a += t; }
    }
    __syncthreads();
    if (tid < NB) g_bbase[tid] = v - s + wpre[wid];
    if (tid == 0) g_off[n] = e;
}

// ---------------- scan phase 3: local scan + base, write offsets/cursors ----------------
__global__ __launch_bounds__(SCAN_B) void scan_p3(int n) {
    __shared__ int wsum[32];
    int i = blockIdx.x * SCAN_B + threadIdx.x;
    int c = (i < n) ? g_cnt[i] : 0;
    int lane = threadIdx.x & 31, wid = threadIdx.x >> 5;
    int v = c;
#pragma unroll
    for (int o = 1; o < 32; o <<= 1) {
        int t = __shfl_up_sync(0xffffffffu, v, o);
        if (lane >= o) v += t;
    }
    if (lane == 31) wsum[wid] = v;
    __syncthreads();
    if (wid == 0) {
        int w = wsum[lane];
#pragma unroll
        for (int o = 1; o < 32; o <<= 1) {
            int t = __shfl_up_sync(0xffffffffu, w, o);
            if (lane >= o) w += t;
        }
        wsum[lane] = w;
    }
    __syncthreads();
    int excl = v - c + (wid > 0 ? wsum[wid - 1] : 0);
    int off = g_bbase[blockIdx.x] + excl;
    if (i < n) { g_off[i] = off; g_cnt[i] = off; }
}

// ---------------- kernel 4: scatter src ids into CSR order ----------------
__global__ void scatter_kernel(const int* __restrict__ ei, int e) {
    int g = blockIdx.x * blockDim.x + threadIdx.x;
    if (g >= e) return;
    int src = ei[g];
    int dst = ei[e + g];
    int pos = atomicAdd(&g_cnt[dst], 1);
    g_src[pos] = src;
}

// ---------------- kernel 5: GEMM h = x@W (FFMA2 packed) + attention halves ----------------
__global__ __launch_bounds__(256) void gemm_kernel(
    const float* __restrict__ x, const float* __restrict__ W,
    const float* __restrict__ att_src, const float* __restrict__ att_dst, int n)
{
    __shared__ float xs[TROWS][KC + 1];
    __shared__ float ws[KC][FOUT];

    int tid = threadIdx.x;
    int tx = tid & 7;
    int ty = tid >> 3;
    int row0 = blockIdx.x * TROWS;

    // accp[r][c] holds 2 packed fp32 accumulators (cols 2c, 2c+1 of this thread's 8)
    unsigned long long accp[4][4];
#pragma unroll
    for (int r = 0; r < 4; r++)
#pragma unroll
        for (int c = 0; c < 4; c++) accp[r][c] = 0ull;

    for (int k0 = 0; k0 < KTOT; k0 += KC) {
#pragma unroll
        for (int i = 0; i < 2; i++) {
            int kk = (tid >> 4) + i * 16;
            int cc = (tid & 15) * 4;
            *reinterpret_cast<float4*>(&ws[kk][cc]) =
                *reinterpret_cast<const float4*>(&W[(k0 + kk) * FOUT + cc]);
        }
        {
            int lr = tid >> 3;
            int kq = (tid & 7) * 4;
#pragma unroll
            for (int i = 0; i < 4; i++) {
                int row = row0 + lr + i * 32;
                float4 v = make_float4(0.f, 0.f, 0.f, 0.f);
                if (row < n)
                    v = *reinterpret_cast<const float4*>(&x[row * KTOT + k0 + kq]);
                xs[lr + i * 32][kq + 0] = v.x;
                xs[lr + i * 32][kq + 1] = v.y;
                xs[lr + i * 32][kq + 2] = v.z;
                xs[lr + i * 32][kq + 3] = v.w;
            }
        }
        __syncthreads();
#pragma unroll
        for (int k = 0; k < KC; k++) {
            // 8 cols = 4 packed pairs, loaded as two 16B vectors
            ulonglong2 w01 = *reinterpret_cast<const ulonglong2*>(&ws[k][tx * 8]);
            ulonglong2 w23 = *reinterpret_cast<const ulonglong2*>(&ws[k][tx * 8 + 4]);
#pragma unroll
            for (int r = 0; r < 4; r++) {
                unsigned xu = __float_as_uint(xs[ty * 4 + r][k]);
                unsigned long long xd;
                asm("mov.b64 %0, {%1, %1};" : "=l"(xd) : "r"(xu));
                FMA2(accp[r][0], w01.x, xd);
                FMA2(accp[r][1], w01.y, xd);
                FMA2(accp[r][2], w23.x, xd);
                FMA2(accp[r][3], w23.y, xd);
            }
        }
        __syncthreads();
    }

    float4 as0 = *reinterpret_cast<const float4*>(&att_src[tx * 8]);
    float4 as1 = *reinterpret_cast<const float4*>(&att_src[tx * 8 + 4]);
    float4 ad0 = *reinterpret_cast<const float4*>(&att_dst[tx * 8]);
    float4 ad1 = *reinterpret_cast<const float4*>(&att_dst[tx * 8 + 4]);
    float as[8] = {as0.x, as0.y, as0.z, as0.w, as1.x, as1.y, as1.z, as1.w};
    float ad[8] = {ad0.x, ad0.y, ad0.z, ad0.w, ad1.x, ad1.y, ad1.z, ad1.w};

#pragma unroll
    for (int r = 0; r < 4; r++) {
        int row = row0 + ty * 4 + r;
        float a[8];
#pragma unroll
        for (int c = 0; c < 4; c++)
            asm("mov.b64 {%0, %1}, %2;" : "=f"(a[2 * c]), "=f"(a[2 * c + 1]) : "l"(accp[r][c]));

        float ps = 0.f, pd = 0.f;
#pragma unroll
        for (int j = 0; j < 8; j++) { ps += a[j] * as[j]; pd += a[j] * ad[j]; }
#pragma unroll
        for (int o = 1; o < 8; o <<= 1) {
            ps += __shfl_xor_sync(0xffffffffu, ps, o);
            pd += __shfl_xor_sync(0xffffffffu, pd, o);
        }
        if (row < n) {
            // fp16 h row (8 halves = 16 B per thread)
            __half2 p0 = __float22half2_rn(make_float2(a[0], a[1]));
            __half2 p1 = __float22half2_rn(make_float2(a[2], a[3]));
            __half2 p2 = __float22half2_rn(make_float2(a[4], a[5]));
            __half2 p3 = __float22half2_rn(make_float2(a[6], a[7]));
            uint4 st;
            st.x = *reinterpret_cast<unsigned*>(&p0);
            st.y = *reinterpret_cast<unsigned*>(&p1);
            st.z = *reinterpret_cast<unsigned*>(&p2);
            st.w = *reinterpret_cast<unsigned*>(&p3);
            *reinterpret_cast<uint4*>(&g_hh[row * FOUT + tx * 8]) = st;
            if (tx == 0) { g_asrc[row] = ps; g_adst[row] = pd; }
        }
    }
}

// ---------------- kernel 6: gather aggregation, fp16 h, 2 edges/iter ----------------
// No max-subtraction: softmax ratio exp(e)/sum(exp(e)) is identical; logits are small.
__global__ __launch_bounds__(256) void aggregate_kernel(
    float* __restrict__ out, const float* __restrict__ bias, int n)
{
    __shared__ int   s_s[8][32];
    __shared__ float p_s[8][32];

    int w = threadIdx.x >> 5;
    int lane = threadIdx.x & 31;
    int half = lane >> 4;
    int l = lane & 15;
    int node = blockIdx.x * 8 + w;
    if (node >= n) return;

    int rs = g_off[node];
    int re = g_off[node + 1];
    float adst = g_adst[node];

    float4 acc = make_float4(0.f, 0.f, 0.f, 0.f);
    float dsum = 0.f;

    for (int base = rs; base < re; base += 32) {
        int cnt = min(32, re - base);
        int s = 0;
        float p = 0.f;
        if (lane < cnt) {
            s = g_src[base + lane];
            float v = g_asrc[s] + adst;
            v = v > 0.f ? v : 0.2f * v;
            p = __expf(v);
        }
        dsum += p;
        s_s[w][lane] = s;
        p_s[w][lane] = p;
        __syncwarp();
        // two edges in flight: half 0 takes even t, half 1 odd t; lane l owns cols l*4..l*4+3
#pragma unroll 4
        for (int t = half; t < cnt; t += 2) {
            int st = s_s[w][t];
            float pt = p_s[w][t];
            uint2 hv = *reinterpret_cast<const uint2*>(&g_hh[(size_t)st * FOUT + l * 4]);
            float2 f01 = __half22float2(*reinterpret_cast<__half2*>(&hv.x));
            float2 f23 = __half22float2(*reinterpret_cast<__half2*>(&hv.y));
            acc.x += pt * f01.x; acc.y += pt * f01.y;
            acc.z += pt * f23.x; acc.w += pt * f23.y;
        }
        __syncwarp();
    }

    // self-loop (half 0 only)
    if (half == 0) {
        float v = g_asrc[node] + adst;
        v = v > 0.f ? v : 0.2f * v;
        float p = __expf(v);
        if (l == 0) dsum += p;
        uint2 hv = *reinterpret_cast<const uint2*>(&g_hh[(size_t)node * FOUT + l * 4]);
        float2 f01 = __half22float2(*reinterpret_cast<__half2*>(&hv.x));
        float2 f23 = __half22float2(*reinterpret_cast<__half2*>(&hv.y));
        acc.x += p * f01.x; acc.y += p * f01.y;
        acc.z += p * f23.x; acc.w += p * f23.y;
    }

#pragma unroll
    for (int o = 16; o > 0; o >>= 1)
        dsum += __shfl_xor_sync(0xffffffffu, dsum, o);

    acc.x += __shfl_down_sync(0xffffffffu, acc.x, 16);
    acc.y += __shfl_down_sync(0xffffffffu, acc.y, 16);
    acc.z += __shfl_down_sync(0xffffffffu, acc.z, 16);
    acc.w += __shfl_down_sync(0xffffffffu, acc.w, 16);

    if (half == 0) {
        float inv = 1.0f / (dsum + 1e-16f);
        float4 b = reinterpret_cast<const float4*>(bias)[l];
        reinterpret_cast<float4*>(out)[(size_t)node * 16 + l] =
            make_float4(acc.x * inv + b.x, acc.y * inv + b.y,
                        acc.z * inv + b.z, acc.w * inv + b.w);
    }
}

// ---------------- launch: fork CSR build ∥ GEMM, join before aggregate ----------------
extern "C" void kernel_launch(void* const* d_in, const int* in_sizes, int n_in,
                              void* d_out, int out_size) {
    const float* x       = (const float*)d_in[0];
    const int*   ei      = (const int*)d_in[1];
    const float* W       = (const float*)d_in[2];
    const float* att_src = (const float*)d_in[3];
    const float* att_dst = (const float*)d_in[4];
    const float* bias    = (const float*)d_in[5];
    float* out = (float*)d_out;

    int n = in_sizes[0] / KTOT;   // 100000
    int e = in_sizes[1] / 2;      // 3200000

    static cudaStream_t s2 = nullptr;
    static cudaEvent_t evFork = nullptr, evJoin = nullptr;
    if (s2 == nullptr) {
        cudaStreamCreateWithFlags(&s2, cudaStreamNonBlocking);
        cudaEventCreateWithFlags(&evFork, cudaEventDisableTiming);
        cudaEventCreateWithFlags(&evJoin, cudaEventDisableTiming);
    }

    // fork: GEMM on side stream, CSR build on origin stream
    cudaEventRecord(evFork, 0);
    cudaStreamWaitEvent(s2, evFork, 0);
    gemm_kernel<<<(n + TROWS - 1) / TROWS, 256, 0, s2>>>(x, W, att_src, att_dst, n);
    cudaEventRecord(evJoin, s2);

    zero_cnt<<<(n + 255) / 256, 256>>>(n);
    hist_kernel<<<(e + 255) / 256, 256>>>(ei, e);
    scan_p1<<<NB, SCAN_B>>>(n);
    scan_p2<<<1, 128>>>(n, e);
    scan_p3<<<NB, SCAN_B>>>(n);
    scatter_kernel<<<(e + 255) / 256, 256>>>(ei, e);

    cudaStreamWaitEvent(0, evJoin, 0);

    aggregate_kernel<<<(n + 7) / 8, 256>>>(out, bias, n);
}